// round 7
// baseline (speedup 1.0000x reference)
#include <cuda_runtime.h>
#include <cuda_bf16.h>
#include <cstdint>

#define NUM_EXPERTS 16
#define BATCH       1024
#define IDIM        512
#define UNITS       512

#define BM 64
#define BN 32
#define BK 32
#define THREADS 128
#define KCHUNKS (IDIM / BK)        // 16
#define MAX_WORK 32                // sum ceil(cnt/64) <= 31
#define ROWS_PAD (MAX_WORK * BM)   // 2048

// A smem: 4 stages x (hi,lo) x 64 rows x 80B
#define A_ROW_B 80
#define A_BUF   (64 * A_ROW_B)     // 5120
#define ASTG    4
// B smem: 2 stages x (hi,lo) x 32 k-rows x 80B
#define B_ROW_B 80
#define B_BUF   (32 * B_ROW_B)     // 2560

// ---------------- device scratch (allocation-free) ----------------
__device__ int g_order[BATCH];
__device__ int g_orderp[ROWS_PAD];
__device__ int g_we[MAX_WORK];
__device__ int g_wstart[MAX_WORK];
__device__ int g_wvalid[MAX_WORK];
__device__ int g_nwork;
__device__ int g_nrowsp;
__device__ uint32_t g_xh[ROWS_PAD * 256];   // bf16x2, padded-gathered x hi
__device__ uint32_t g_xl[ROWS_PAD * 256];   // bf16x2, residual lo

// ---------------------------------------------------------------------------
// prep: counting sort by expert, padded order, work list (BM=64 tiles).
// ---------------------------------------------------------------------------
__global__ void prep_kernel(const void* idx_raw)
{
    const int* i32 = (const int*)idx_raw;
    __shared__ int cnt[NUM_EXPERTS];
    __shared__ int off[NUM_EXPERTS + 1];
    __shared__ int offp[NUM_EXPERTS + 1];
    __shared__ int cur[NUM_EXPERTS];
    __shared__ int odd_nonzero;

    int t = threadIdx.x;
    if (t == 0) odd_nonzero = 0;
    if (t < NUM_EXPERTS) { cnt[t] = 0; cur[t] = 0; }
    __syncthreads();

    if (t < 512) {
        if (i32[2 * t + 1] != 0) atomicOr(&odd_nonzero, 1);
    }
    __syncthreads();

    int e;
    if (odd_nonzero) e = i32[t];          // int32 data
    else             e = i32[2 * t];      // int64 data, low word
    e &= (NUM_EXPERTS - 1);

    atomicAdd(&cnt[e], 1);
    __syncthreads();

    if (t == 0) {
        int s = 0, sp = 0, nw = 0;
        for (int i = 0; i < NUM_EXPERTS; i++) {
            off[i] = s;
            offp[i] = sp;
            int c = cnt[i];
            int tiles = (c + BM - 1) / BM;
            for (int j = 0; j < tiles; j++) {
                g_we[nw] = i;
                g_wstart[nw] = sp + j * BM;
                int v = c - j * BM;
                g_wvalid[nw] = (v < BM) ? v : BM;
                nw++;
            }
            s += c;
            sp += tiles * BM;
        }
        off[NUM_EXPERTS] = s;
        offp[NUM_EXPERTS] = sp;
        g_nwork = nw;
        g_nrowsp = sp;
    }
    __syncthreads();

    int p = atomicAdd(&cur[e], 1);
    g_order[off[e] + p] = t;
    __syncthreads();

    int total = offp[NUM_EXPERTS];
    for (int s = t; s < total; s += blockDim.x) {
        int ee = 0;
        while (s >= offp[ee + 1]) ee++;
        int local = s - offp[ee];
        int c = cnt[ee];
        int src = (local < c) ? local : (c - 1);
        g_orderp[s] = g_order[off[ee] + src];
    }
}

// ---------------- conversion helpers ----------------
__device__ __forceinline__ uint32_t pack_bf16(float lo, float hi)
{
    uint32_t r;
    asm("cvt.rn.bf16x2.f32 %0, %1, %2;" : "=r"(r) : "f"(hi), "f"(lo));
    return r;
}
__device__ __forceinline__ void cvt8(const float* f, uint4& H, uint4& L)
{
    uint32_t h[4], l[4];
#pragma unroll
    for (int i = 0; i < 4; i++) {
        float a = f[2 * i], b = f[2 * i + 1];
        uint32_t hp = pack_bf16(a, b);
        float ra = a - __uint_as_float(hp << 16);
        float rb = b - __uint_as_float(hp & 0xFFFF0000u);
        h[i] = hp;
        l[i] = pack_bf16(ra, rb);
    }
    H = make_uint4(h[0], h[1], h[2], h[3]);
    L = make_uint4(l[0], l[1], l[2], l[3]);
}

// ---------------------------------------------------------------------------
// split kernel: gathered+padded x -> bf16 hi/lo. grid 1024 x 256 threads.
// thread i handles 4 fp32 (one float4).
// ---------------------------------------------------------------------------
__global__ __launch_bounds__(256)
void split_kernel(const float* __restrict__ x)
{
    int i = blockIdx.x * blockDim.x + threadIdx.x;   // 0 .. 262143
    int row = i >> 7;                 // /128 quads per row
    if (row >= g_nrowsp) return;
    int q = i & 127;                  // quad within row
    int src = g_orderp[row];
    float4 v = *(const float4*)(x + (size_t)src * IDIM + q * 4);

    uint32_t h0 = pack_bf16(v.x, v.y);
    float r0 = v.x - __uint_as_float(h0 << 16);
    float r1 = v.y - __uint_as_float(h0 & 0xFFFF0000u);
    uint32_t l0 = pack_bf16(r0, r1);
    uint32_t h1 = pack_bf16(v.z, v.w);
    float r2 = v.z - __uint_as_float(h1 << 16);
    float r3 = v.w - __uint_as_float(h1 & 0xFFFF0000u);
    uint32_t l1 = pack_bf16(r2, r3);

    size_t o = (size_t)row * 256 + q * 2;
    *(uint2*)&g_xh[o] = make_uint2(h0, h1);
    *(uint2*)&g_xl[o] = make_uint2(l0, l1);
}

// ---------------- mma / ldmatrix / cp.async helpers ----------------
__device__ __forceinline__ uint32_t smem_u32(const void* p)
{ return (uint32_t)__cvta_generic_to_shared(p); }

__device__ __forceinline__ void ldsm4(uint32_t addr, uint32_t* r)
{
    asm volatile("ldmatrix.sync.aligned.m8n8.x4.shared.b16 {%0,%1,%2,%3}, [%4];"
                 : "=r"(r[0]), "=r"(r[1]), "=r"(r[2]), "=r"(r[3]) : "r"(addr));
}
__device__ __forceinline__ void ldsm4t(uint32_t addr, uint32_t* r)
{
    asm volatile("ldmatrix.sync.aligned.m8n8.x4.trans.shared.b16 {%0,%1,%2,%3}, [%4];"
                 : "=r"(r[0]), "=r"(r[1]), "=r"(r[2]), "=r"(r[3]) : "r"(addr));
}
__device__ __forceinline__ void mma16816(float* c, const uint32_t* a, const uint32_t* b)
{
    asm volatile("mma.sync.aligned.m16n8k16.row.col.f32.bf16.bf16.f32 "
                 "{%0,%1,%2,%3}, {%4,%5,%6,%7}, {%8,%9}, {%0,%1,%2,%3};"
                 : "+f"(c[0]), "+f"(c[1]), "+f"(c[2]), "+f"(c[3])
                 : "r"(a[0]), "r"(a[1]), "r"(a[2]), "r"(a[3]),
                   "r"(b[0]), "r"(b[1]));
}
__device__ __forceinline__ void cp16(uint32_t sdst, const void* gsrc)
{ asm volatile("cp.async.cg.shared.global [%0], [%1], 16;" :: "r"(sdst), "l"(gsrc)); }
__device__ __forceinline__ void cp_commit()
{ asm volatile("cp.async.commit_group;"); }
__device__ __forceinline__ void cp_wait2()
{ asm volatile("cp.async.wait_group 2;"); }

// ---------------------------------------------------------------------------
// grouped GEMM, tensor cores, pre-split A via cp.async (4 stages),
// in-kernel W convert with 2-ahead register prefetch (2 stages).
// ---------------------------------------------------------------------------
__global__ __launch_bounds__(THREADS)
void gemm_kernel(const float* __restrict__ ws,
                 const float* __restrict__ bs,
                 float* __restrict__ out)
{
    const int by = blockIdx.y;
    if (by >= g_nwork) return;

    const int e     = g_we[by];
    const int start = g_wstart[by];
    const int valid = g_wvalid[by];
    const int n0    = blockIdx.x * BN;

    __shared__ __align__(16) char sA[ASTG][2][A_BUF];   // [stage][hi/lo]
    __shared__ __align__(16) char sB[2][2][B_BUF];      // [stage][hi/lo]
    __shared__ float s_bias[BN];

    const int t    = threadIdx.x;
    const int lane = t & 31;
    const int w    = t >> 5;
    const int wm   = w & 1;
    const int wn   = w >> 1;

    if (t < BN) s_bias[t] = bs[e * UNITS + n0 + t];

    // ---- A producer: thread covers row t>>1, 2 segs of 16B (hi and lo) ----
    const int a_row = t >> 1;
    const int s0    = (t & 1) * 2;                 // seg 0..3, 16B each (8 bf16)
    const char* gAh = (const char*)g_xh + ((size_t)(start + a_row) * 512) * 2 + s0 * 16;
    const char* gAl = (const char*)g_xl + ((size_t)(start + a_row) * 512) * 2 + s0 * 16;
    const uint32_t a_st = (uint32_t)(a_row * A_ROW_B + s0 * 16);

    // ---- B producer: thread covers k-row t>>2, n-octet (t&3)*8 ----
    const int b_k  = t >> 2;
    const int b_nq = (t & 3) * 8;
    const float* wrow = ws + ((size_t)e * IDIM + b_k) * UNITS + n0 + b_nq;
    const uint32_t b_st = (uint32_t)(b_k * B_ROW_B + (t & 3) * 16);

    // ---- consumer lane offsets ----
    const uint32_t a_lane = (uint32_t)((lane & 15) * A_ROW_B + ((lane >> 4) & 1) * 16);
    const uint32_t b_lane = (uint32_t)(((lane & 7) + ((lane >> 3) & 1) * 8) * B_ROW_B
                                      + ((lane >> 4) & 1) * 16);

    float acc[2][2][4];
#pragma unroll
    for (int i = 0; i < 2; i++)
#pragma unroll
        for (int j = 0; j < 2; j++)
#pragma unroll
            for (int q = 0; q < 4; q++) acc[i][j][q] = 0.0f;

    // helper lambdas -------------------------------------------------------
    auto issueA = [&](int c, int stg) {
        // chunk c covers k-bytes [c*64, c*64+64) of the bf16 row
        const char* ph = gAh + c * 64;
        const char* pl = gAl + c * 64;
        uint32_t dh = smem_u32(&sA[stg][0][0]) + a_st;
        uint32_t dl = smem_u32(&sA[stg][1][0]) + a_st;
        cp16(dh,      ph);
        cp16(dh + 16, ph + 16);
        cp16(dl,      pl);
        cp16(dl + 16, pl + 16);
    };

    float pb[2][8];
    auto loadB = [&](int c, int buf) {
        float4 u = *(const float4*)(wrow + (size_t)c * BK * UNITS);
        float4 v = *(const float4*)(wrow + (size_t)c * BK * UNITS + 4);
        pb[buf][0]=u.x; pb[buf][1]=u.y; pb[buf][2]=u.z; pb[buf][3]=u.w;
        pb[buf][4]=v.x; pb[buf][5]=v.y; pb[buf][6]=v.z; pb[buf][7]=v.w;
    };
    auto stsB = [&](int buf, int stg) {
        uint4 H, L;
        cvt8(pb[buf], H, L);
        *(uint4*)(&sB[stg][0][b_st]) = H;
        *(uint4*)(&sB[stg][1][b_st]) = L;
    };

    // ---- prologue ----
    issueA(0, 0); cp_commit();
    issueA(1, 1); cp_commit();
    issueA(2, 2); cp_commit();
    loadB(0, 0);
    loadB(1, 1);
    stsB(0, 0);
    cp_wait2();
    __syncthreads();

    // ---- main loop ----
    for (int c = 0; c < KCHUNKS; c++) {
        if (c + 3 < KCHUNKS) issueA(c + 3, (c + 3) & 3);
        cp_commit();
        if (c + 2 < KCHUNKS) loadB(c + 2, c & 1);

        // compute chunk c
        const uint32_t Ah = smem_u32(&sA[c & 3][0][0]);
        const uint32_t Al = smem_u32(&sA[c & 3][1][0]);
        const uint32_t Bh = smem_u32(&sB[c & 1][0][0]);
        const uint32_t Bl = smem_u32(&sB[c & 1][1][0]);

#pragma unroll
        for (int ks = 0; ks < 2; ks++) {
            uint32_t aH[2][4], aL[2][4], bH[4], bL[4];
#pragma unroll
            for (int i = 0; i < 2; i++) {
                uint32_t ao = (uint32_t)(wm * 32 * A_ROW_B + i * 16 * A_ROW_B + ks * 32) + a_lane;
                ldsm4(Ah + ao, aH[i]);
                ldsm4(Al + ao, aL[i]);
            }
            {
                uint32_t bo = (uint32_t)(ks * 16 * B_ROW_B + wn * 32) + b_lane;
                ldsm4t(Bh + bo, bH);
                ldsm4t(Bl + bo, bL);
            }
#pragma unroll
            for (int i = 0; i < 2; i++) {
#pragma unroll
                for (int j = 0; j < 2; j++) {
                    mma16816(acc[i][j], aH[i], &bH[j * 2]);
                    mma16816(acc[i][j], aH[i], &bL[j * 2]);
                    mma16816(acc[i][j], aL[i], &bH[j * 2]);
                }
            }
        }

        if (c + 1 < KCHUNKS) {
            stsB((c + 1) & 1, (c + 1) & 1);
            cp_wait2();
            __syncthreads();
        }
    }

    // ---- epilogue: bias + relu, masked scatter ----
#pragma unroll
    for (int i = 0; i < 2; i++) {
        int r0 = wm * 32 + i * 16 + (lane >> 2);
        int r1 = r0 + 8;
        int gr0 = (r0 < valid) ? g_orderp[start + r0] : -1;
        int gr1 = (r1 < valid) ? g_orderp[start + r1] : -1;
#pragma unroll
        for (int j = 0; j < 2; j++) {
            int col = wn * 16 + j * 8 + (lane & 3) * 2;
            float b0 = s_bias[col], b1 = s_bias[col + 1];
            if (gr0 >= 0) {
                float2 v;
                v.x = fmaxf(acc[i][j][0] + b0, 0.0f);
                v.y = fmaxf(acc[i][j][1] + b1, 0.0f);
                *(float2*)&out[(size_t)gr0 * UNITS + n0 + col] = v;
            }
            if (gr1 >= 0) {
                float2 v;
                v.x = fmaxf(acc[i][j][2] + b0, 0.0f);
                v.y = fmaxf(acc[i][j][3] + b1, 0.0f);
                *(float2*)&out[(size_t)gr1 * UNITS + n0 + col] = v;
            }
        }
    }
}

extern "C" void kernel_launch(void* const* d_in, const int* in_sizes, int n_in,
                              void* d_out, int out_size)
{
    const float* x   = (const float*)d_in[0];
    const void*  idx = d_in[1];
    const float* ws  = (const float*)d_in[2];
    const float* bs  = (const float*)d_in[3];
    float* out = (float*)d_out;

    prep_kernel<<<1, BATCH>>>(idx);
    split_kernel<<<1024, 256>>>(x);
    dim3 grid(UNITS / BN, MAX_WORK);
    gemm_kernel<<<grid, THREADS>>>(ws, bs, out);
}

// round 8
// speedup vs baseline: 1.1310x; 1.1310x over previous
#include <cuda_runtime.h>
#include <cuda_bf16.h>
#include <cstdint>

#define NUM_EXPERTS 16
#define BATCH       1024
#define IDIM        512
#define UNITS       512

#define BM 32
#define BN 64
#define BK 32
#define THREADS 256
#define KCHUNKS (IDIM / BK)        // 16
#define MAX_WORK 48                // sum ceil(cnt/32) <= 47
#define ROWS_PAD (MAX_WORK * BM)   // 1536

// A smem: 4 stages x (hi,lo) x 32 rows x 80B (64 data + 16 pad)
#define A_ROW_B 80
#define A_BUF   (BM * A_ROW_B)     // 2560
#define ASTG    4
// B smem: 2 stages x (hi,lo) x 32 k-rows x 144B (128 data + 16 pad)
#define B_ROW_B 144
#define B_BUF   (32 * B_ROW_B)     // 4608

// ---------------- device scratch (allocation-free) ----------------
__device__ int g_orderp[ROWS_PAD];
__device__ int g_we[MAX_WORK];
__device__ int g_wstart[MAX_WORK];
__device__ int g_wvalid[MAX_WORK];
__device__ int g_nwork;
__device__ int g_nrowsp;
__device__ uint32_t g_xh[ROWS_PAD * 256];   // bf16x2, padded-gathered x hi
__device__ uint32_t g_xl[ROWS_PAD * 256];   // bf16x2, residual lo

// ---------------------------------------------------------------------------
// prep: warp-aggregated counting sort by expert, padded order, work list.
// One atomic round; dtype probe via syncthreads_or.
// ---------------------------------------------------------------------------
__global__ void prep_kernel(const void* idx_raw)
{
    const int* i32 = (const int*)idx_raw;
    __shared__ int cnt[NUM_EXPERTS];
    __shared__ int offp[NUM_EXPERTS + 1];

    const int t    = threadIdx.x;
    const int lane = t & 31;

    if (t < NUM_EXPERTS) cnt[t] = 0;

    int odd = 0;
    if (t < 512) odd = (i32[2 * t + 1] != 0);
    int any_odd = __syncthreads_or(odd);    // also acts as the barrier for cnt init

    int e = any_odd ? i32[t] : i32[2 * t];  // int32 data vs int64 low word
    e &= (NUM_EXPERTS - 1);

    // warp-aggregated rank within expert
    unsigned m   = __match_any_sync(0xFFFFFFFFu, e);
    int lead     = __ffs(m) - 1;
    int lrank    = __popc(m & ((1u << lane) - 1));
    int base     = 0;
    if (lane == lead) base = atomicAdd(&cnt[e], __popc(m));
    base = __shfl_sync(0xFFFFFFFFu, base, lead);
    int pos = base + lrank;
    __syncthreads();

    if (t == 0) {
        int sp = 0, nw = 0;
        for (int i = 0; i < NUM_EXPERTS; i++) {
            offp[i] = sp;
            int c = cnt[i];
            int tiles = (c + BM - 1) / BM;
            for (int j = 0; j < tiles; j++) {
                g_we[nw] = i;
                g_wstart[nw] = sp + j * BM;
                int v = c - j * BM;
                g_wvalid[nw] = (v < BM) ? v : BM;
                nw++;
            }
            sp += tiles * BM;
        }
        offp[NUM_EXPERTS] = sp;
        g_nwork  = nw;
        g_nrowsp = sp;
    }
    __syncthreads();

    g_orderp[offp[e] + pos] = t;            // real entries
    __syncthreads();

    // pad entries duplicate the expert's rank-0 row
    int total = offp[NUM_EXPERTS];
    for (int s = t; s < total; s += blockDim.x) {
        int ee = 0;
        while (s >= offp[ee + 1]) ee++;
        if (s - offp[ee] >= cnt[ee])
            g_orderp[s] = g_orderp[offp[ee]];
    }
}

// ---------------- conversion helpers ----------------
__device__ __forceinline__ uint32_t pack_bf16(float lo, float hi)
{
    uint32_t r;
    asm("cvt.rn.bf16x2.f32 %0, %1, %2;" : "=r"(r) : "f"(hi), "f"(lo));
    return r;
}
__device__ __forceinline__ void cvt8(const float* f, uint4& H, uint4& L)
{
    uint32_t h[4], l[4];
#pragma unroll
    for (int i = 0; i < 4; i++) {
        float a = f[2 * i], b = f[2 * i + 1];
        uint32_t hp = pack_bf16(a, b);
        float ra = a - __uint_as_float(hp << 16);
        float rb = b - __uint_as_float(hp & 0xFFFF0000u);
        h[i] = hp;
        l[i] = pack_bf16(ra, rb);
    }
    H = make_uint4(h[0], h[1], h[2], h[3]);
    L = make_uint4(l[0], l[1], l[2], l[3]);
}

// ---------------------------------------------------------------------------
// split kernel: gathered+padded x -> bf16 hi/lo.
// ---------------------------------------------------------------------------
__global__ __launch_bounds__(256)
void split_kernel(const float* __restrict__ x)
{
    int i = blockIdx.x * blockDim.x + threadIdx.x;
    int row = i >> 7;                 // 128 quads per row
    if (row >= g_nrowsp) return;
    int q = i & 127;
    int src = g_orderp[row];
    float4 v = *(const float4*)(x + (size_t)src * IDIM + q * 4);

    uint32_t h0 = pack_bf16(v.x, v.y);
    float r0 = v.x - __uint_as_float(h0 << 16);
    float r1 = v.y - __uint_as_float(h0 & 0xFFFF0000u);
    uint32_t l0 = pack_bf16(r0, r1);
    uint32_t h1 = pack_bf16(v.z, v.w);
    float r2 = v.z - __uint_as_float(h1 << 16);
    float r3 = v.w - __uint_as_float(h1 & 0xFFFF0000u);
    uint32_t l1 = pack_bf16(r2, r3);

    size_t o = (size_t)row * 256 + q * 2;
    *(uint2*)&g_xh[o] = make_uint2(h0, h1);
    *(uint2*)&g_xl[o] = make_uint2(l0, l1);
}

// ---------------- mma / ldmatrix / cp.async helpers ----------------
__device__ __forceinline__ uint32_t smem_u32(const void* p)
{ return (uint32_t)__cvta_generic_to_shared(p); }

__device__ __forceinline__ void ldsm4(uint32_t addr, uint32_t* r)
{
    asm volatile("ldmatrix.sync.aligned.m8n8.x4.shared.b16 {%0,%1,%2,%3}, [%4];"
                 : "=r"(r[0]), "=r"(r[1]), "=r"(r[2]), "=r"(r[3]) : "r"(addr));
}
__device__ __forceinline__ void ldsm4t(uint32_t addr, uint32_t* r)
{
    asm volatile("ldmatrix.sync.aligned.m8n8.x4.trans.shared.b16 {%0,%1,%2,%3}, [%4];"
                 : "=r"(r[0]), "=r"(r[1]), "=r"(r[2]), "=r"(r[3]) : "r"(addr));
}
__device__ __forceinline__ void mma16816(float* c, const uint32_t* a, const uint32_t* b)
{
    asm volatile("mma.sync.aligned.m16n8k16.row.col.f32.bf16.bf16.f32 "
                 "{%0,%1,%2,%3}, {%4,%5,%6,%7}, {%8,%9}, {%0,%1,%2,%3};"
                 : "+f"(c[0]), "+f"(c[1]), "+f"(c[2]), "+f"(c[3])
                 : "r"(a[0]), "r"(a[1]), "r"(a[2]), "r"(a[3]),
                   "r"(b[0]), "r"(b[1]));
}
__device__ __forceinline__ void cp16(uint32_t sdst, const void* gsrc)
{ asm volatile("cp.async.cg.shared.global [%0], [%1], 16;" :: "r"(sdst), "l"(gsrc)); }
__device__ __forceinline__ void cp_commit()
{ asm volatile("cp.async.commit_group;"); }
__device__ __forceinline__ void cp_wait2()
{ asm volatile("cp.async.wait_group 2;"); }

// ---------------------------------------------------------------------------
// grouped GEMM, tensor cores. BM=32 x BN=64 x BK=32, 256 threads (8 warps,
// warp tile m16 x n16). A: pre-split bf16 via 4-stage cp.async.
// B: fp32 W, 2-ahead register prefetch + in-kernel convert, 2 stages.
// ---------------------------------------------------------------------------
__global__ __launch_bounds__(THREADS)
void gemm_kernel(const float* __restrict__ ws,
                 const float* __restrict__ bs,
                 float* __restrict__ out)
{
    const int by = blockIdx.y;
    if (by >= g_nwork) return;

    const int e     = g_we[by];
    const int start = g_wstart[by];
    const int valid = g_wvalid[by];
    const int n0    = blockIdx.x * BN;

    __shared__ __align__(16) char sA[ASTG][2][A_BUF];   // [stage][hi/lo]
    __shared__ __align__(16) char sB[2][2][B_BUF];      // [stage][hi/lo]
    __shared__ float s_bias[BN];

    const int t    = threadIdx.x;
    const int lane = t & 31;
    const int w    = t >> 5;
    const int wm   = w & 1;      // m warp: rows wm*16..+15
    const int wn   = w >> 1;     // n warp: cols wn*16..+15

    if (t < BN) s_bias[t] = bs[e * UNITS + n0 + t];

    // ---- A producer: row = t>>3, seg = t&7 (segs 0-3 hi, 4-7 lo) ----
    const int a_row  = t >> 3;
    const int a_seg  = t & 7;
    const int a_term = a_seg >> 2;            // 0 hi, 1 lo
    const int a_s16  = (a_seg & 3) * 16;      // byte offset within 64B chunk-row
    const char* gA = (const char*)(a_term ? g_xl : g_xh)
                     + (size_t)(start + a_row) * 1024 + a_s16;
    const uint32_t a_st = (uint32_t)(a_row * A_ROW_B + a_s16);

    // ---- B producer: k-row = t>>3, n-octet = (t&7)*8 ----
    const int b_k  = t >> 3;
    const int b_nq = (t & 7) * 8;
    const float* wrow = ws + ((size_t)e * IDIM + b_k) * UNITS + n0 + b_nq;
    const uint32_t b_st = (uint32_t)(b_k * B_ROW_B + (t & 7) * 16);

    // ---- consumer lane offsets ----
    const uint32_t a_lane = (uint32_t)((lane & 15) * A_ROW_B + (lane >> 4) * 16);
    const uint32_t b_lane = (uint32_t)((lane & 15) * B_ROW_B + (lane >> 4) * 16);

    float acc[2][4];
#pragma unroll
    for (int j = 0; j < 2; j++)
#pragma unroll
        for (int q = 0; q < 4; q++) acc[j][q] = 0.0f;

    // helpers --------------------------------------------------------------
    auto issueA = [&](int c, int stg) {
        cp16(smem_u32(&sA[stg][a_term][0]) + a_st, gA + c * 64);
    };

    float pb[2][8];
    auto loadB = [&](int c, int buf) {
        float4 u = *(const float4*)(wrow + (size_t)c * BK * UNITS);
        float4 v = *(const float4*)(wrow + (size_t)c * BK * UNITS + 4);
        pb[buf][0]=u.x; pb[buf][1]=u.y; pb[buf][2]=u.z; pb[buf][3]=u.w;
        pb[buf][4]=v.x; pb[buf][5]=v.y; pb[buf][6]=v.z; pb[buf][7]=v.w;
    };
    auto stsB = [&](int buf, int stg) {
        uint4 H, L;
        cvt8(pb[buf], H, L);
        *(uint4*)(&sB[stg][0][b_st]) = H;
        *(uint4*)(&sB[stg][1][b_st]) = L;
    };

    // ---- prologue ----
    issueA(0, 0); cp_commit();
    issueA(1, 1); cp_commit();
    issueA(2, 2); cp_commit();
    loadB(0, 0);
    loadB(1, 1);
    stsB(0, 0);
    cp_wait2();
    __syncthreads();

    // ---- main loop ----
    for (int c = 0; c < KCHUNKS; c++) {
        if (c + 3 < KCHUNKS) issueA(c + 3, (c + 3) & 3);
        cp_commit();
        if (c + 2 < KCHUNKS) loadB(c + 2, c & 1);

        const uint32_t Ah = smem_u32(&sA[c & 3][0][0]);
        const uint32_t Al = smem_u32(&sA[c & 3][1][0]);
        const uint32_t Bh = smem_u32(&sB[c & 1][0][0]);
        const uint32_t Bl = smem_u32(&sB[c & 1][1][0]);

#pragma unroll
        for (int ks = 0; ks < 2; ks++) {
            uint32_t aH[4], aL[4], bH[4], bL[4];
            uint32_t ao = (uint32_t)(wm * 16 * A_ROW_B + ks * 32) + a_lane;
            ldsm4(Ah + ao, aH);
            ldsm4(Al + ao, aL);
            uint32_t bo = (uint32_t)(ks * 16 * B_ROW_B + wn * 32) + b_lane;
            ldsm4t(Bh + bo, bH);
            ldsm4t(Bl + bo, bL);
#pragma unroll
            for (int j = 0; j < 2; j++) {
                mma16816(acc[j], aH, &bH[j * 2]);
                mma16816(acc[j], aH, &bL[j * 2]);
                mma16816(acc[j], aL, &bH[j * 2]);
            }
        }

        if (c + 1 < KCHUNKS) {
            stsB((c + 1) & 1, (c + 1) & 1);
            cp_wait2();
            __syncthreads();
        }
    }

    // ---- epilogue: bias + relu, masked scatter ----
    {
        int r0 = wm * 16 + (lane >> 2);
        int r1 = r0 + 8;
        int gr0 = (r0 < valid) ? g_orderp[start + r0] : -1;
        int gr1 = (r1 < valid) ? g_orderp[start + r1] : -1;
#pragma unroll
        for (int j = 0; j < 2; j++) {
            int col = wn * 16 + j * 8 + (lane & 3) * 2;
            float b0 = s_bias[col], b1 = s_bias[col + 1];
            if (gr0 >= 0) {
                float2 v;
                v.x = fmaxf(acc[j][0] + b0, 0.0f);
                v.y = fmaxf(acc[j][1] + b1, 0.0f);
                *(float2*)&out[(size_t)gr0 * UNITS + n0 + col] = v;
            }
            if (gr1 >= 0) {
                float2 v;
                v.x = fmaxf(acc[j][2] + b0, 0.0f);
                v.y = fmaxf(acc[j][3] + b1, 0.0f);
                *(float2*)&out[(size_t)gr1 * UNITS + n0 + col] = v;
            }
        }
    }
}

extern "C" void kernel_launch(void* const* d_in, const int* in_sizes, int n_in,
                              void* d_out, int out_size)
{
    const float* x   = (const float*)d_in[0];
    const void*  idx = d_in[1];
    const float* ws  = (const float*)d_in[2];
    const float* bs  = (const float*)d_in[3];
    float* out = (float*)d_out;

    prep_kernel<<<1, 1024>>>(idx);
    split_kernel<<<(ROWS_PAD * 128 + 255) / 256, 256>>>(x);
    dim3 grid(UNITS / BN, MAX_WORK);
    gemm_kernel<<<grid, THREADS>>>(ws, bs, out);
}